// round 3
// baseline (speedup 1.0000x reference)
#include <cuda_runtime.h>
#include <math.h>
#include <stdint.h>

// ---------------------------------------------------------------------------
// Problem constants
// ---------------------------------------------------------------------------
#define Bn   4
#define Cc   192
#define C2   384
#define Hh   96
#define Ww   96
#define HW   (Hh*Ww)          // 9216
#define NH   8
#define HD   24
#define Gg   8
#define CG   24

// scratch offsets (floats)
#define OFF_QKV1  0ul
#define OFF_QKV   14155776ul
#define OFF_CAT   28311552ul
#define OFF_SIG   42467328ul
#define OFF_SC    56623104ul
#define OFF_POOL  70778880ul
#define OFF_K2    74317824ul
#define OFF_OFF   77568000ul
#define OFF_FEAT  78231552ul
#define OFF_K     85309440ul
#define OFF_AO    92387328ul
#define OFF_QN    99465216ul
#define OFF_KN    99465984ul
#define OFF_ATTN  99466752ul
#define SCRATCH_TOTAL 99485184ul

__device__ float g_scratch[SCRATCH_TOTAL];

// ---------------------------------------------------------------------------
// tf32 helpers
// ---------------------------------------------------------------------------
__device__ __forceinline__ float f2tf32(float x) {
    uint32_t u;
    asm("cvt.rna.tf32.f32 %0, %1;" : "=r"(u) : "f"(x));
    return __uint_as_float(u);
}

__device__ __forceinline__ void mma_16x8x8(float* c, const uint32_t* a,
                                           uint32_t b0, uint32_t b1) {
    asm volatile(
        "mma.sync.aligned.m16n8k8.row.col.f32.tf32.tf32.f32 "
        "{%0,%1,%2,%3}, {%4,%5,%6,%7}, {%8,%9}, {%0,%1,%2,%3};\n"
        : "+f"(c[0]), "+f"(c[1]), "+f"(c[2]), "+f"(c[3])
        : "r"(a[0]), "r"(a[1]), "r"(a[2]), "r"(a[3]), "r"(b0), "r"(b1));
}

// bank swizzle: keeps both tile stores and fragment loads conflict-free with
// zero padding.  x' = x ^ (((k&3) ^ ((k>>2)&3)) << 3)
__device__ __forceinline__ int SW(int k, int x) {
    return x ^ ((((k) & 3) ^ (((k) >> 2) & 3)) << 3);
}

// ---------------------------------------------------------------------------
// tf32 tensor-core implicit-GEMM conv, v2.
// BM = 32*FM (128 or 32), BN = 256, BK = 16, 256 threads = 8 warps (2M x 4N),
// warp tile (16*FM) x 64.  Double-buffered, swizzled, zero-pad smem (48KB).
// ---------------------------------------------------------------------------
template<int KS, int FM>
__global__ __launch_bounds__(256)
void conv_mma2(const float* __restrict__ Wt,
               const float* __restrict__ X,
               float* __restrict__ Y,
               const float* __restrict__ bias,
               const float* __restrict__ mul,
               int M, int Cin, int IH, int IW,
               int OH, int OW, int pad, int relu_in)
{
    constexpr int BM   = 32 * FM;
    constexpr int BN   = 256;
    constexpr int BK   = 16;
    constexpr int AELE = BM * BK / 4;          // float4 elements of A tile
    constexpr int AIT  = (AELE + 255) / 256;

    __shared__ float As[2][BK * BM];
    __shared__ float Bs[2][BK * BN];

    const int N  = OH * OW;
    const int K  = Cin * KS * KS;
    const int bz = blockIdx.z;
    const int m0 = blockIdx.y * BM;
    const int n0 = blockIdx.x * BN;

    const int tid  = threadIdx.x;
    const int wid  = tid >> 5;
    const int lane = tid & 31;
    const int wm   = wid & 1;
    const int wn   = wid >> 1;
    const int mbase = wm * (16 * FM);
    const int nbase = wn * 64;
    const int lg = lane >> 2;
    const int lt = lane & 3;

    const float* Xb = X + (size_t)bz * Cin * IH * IW;

    float acc[FM][8][4];
    #pragma unroll
    for (int f = 0; f < FM; ++f)
        #pragma unroll
        for (int nf = 0; nf < 8; ++nf)
            #pragma unroll
            for (int r = 0; r < 4; ++r) acc[f][nf][r] = 0.f;

    const int gn = n0 + tid;
    const bool nvalid = gn < N;
    int oy = 0, ox = 0;
    if (KS == 3) {
        int g = nvalid ? gn : 0;
        oy = g / OW; ox = g - oy * OW;
    }

    float4 aReg[AIT];
    float  bReg[16];

    auto ldA = [&](int k0) {
        #pragma unroll
        for (int r = 0; r < AIT; ++r) {
            int e = tid + r * 256;
            float4 v = make_float4(0.f, 0.f, 0.f, 0.f);
            if (AELE >= 256 * (r + 1) || e < AELE) {
                int m  = e >> 2;
                int kq = e & 3;
                int gm = m0 + m;
                if (gm < M)
                    v = *reinterpret_cast<const float4*>(Wt + (size_t)gm * K + k0 + kq * 4);
            }
            aReg[r] = v;
        }
    };
    auto stA = [&](int buf) {
        #pragma unroll
        for (int r = 0; r < AIT; ++r) {
            int e = tid + r * 256;
            if (AELE >= 256 * (r + 1) || e < AELE) {
                int m  = e >> 2;
                int kq = e & 3;
                float vv[4] = {aReg[r].x, aReg[r].y, aReg[r].z, aReg[r].w};
                #pragma unroll
                for (int j = 0; j < 4; ++j) {
                    int k = kq * 4 + j;
                    As[buf][k * BM + SW(k, m)] = f2tf32(vv[j]);
                }
            }
        }
    };
    auto ldB = [&](int k0) {
        if (KS == 1) {
            #pragma unroll
            for (int k = 0; k < 16; ++k) {
                float v = nvalid ? Xb[(size_t)(k0 + k) * N + gn] : 0.f;
                if (relu_in) v = fmaxf(v, 0.f);
                bReg[k] = v;
            }
        } else {
            int ic = k0 / 9;
            int t  = k0 - ic * 9;
            #pragma unroll
            for (int k = 0; k < 16; ++k) {
                float v = 0.f;
                if (nvalid) {
                    int tdy = (t >= 6) ? 2 : ((t >= 3) ? 1 : 0);
                    int tdx = t - 3 * tdy;
                    int iy = oy + tdy - pad;
                    int ix = ox + tdx - pad;
                    if (iy >= 0 && iy < IH && ix >= 0 && ix < IW)
                        v = Xb[((size_t)ic * IH + iy) * IW + ix];
                    if (relu_in) v = fmaxf(v, 0.f);
                }
                bReg[k] = v;
                if (++t == 9) { t = 0; ++ic; }
            }
        }
    };
    auto stB = [&](int buf) {
        #pragma unroll
        for (int k = 0; k < 16; ++k)
            Bs[buf][k * BN + SW(k, tid)] = f2tf32(bReg[k]);
    };
    auto compute = [&](int buf) {
        #pragma unroll
        for (int ks = 0; ks < 2; ++ks) {
            const int krA = ks * 8 + lt;
            const int krB = krA + 4;
            uint32_t a[FM][4];
            #pragma unroll
            for (int f = 0; f < FM; ++f) {
                int mr = mbase + f * 16 + lg;
                a[f][0] = __float_as_uint(As[buf][krA * BM + SW(krA, mr)]);
                a[f][1] = __float_as_uint(As[buf][krA * BM + SW(krA, mr + 8)]);
                a[f][2] = __float_as_uint(As[buf][krB * BM + SW(krB, mr)]);
                a[f][3] = __float_as_uint(As[buf][krB * BM + SW(krB, mr + 8)]);
            }
            #pragma unroll
            for (int nf = 0; nf < 8; ++nf) {
                int nc = nbase + nf * 8 + lg;
                uint32_t b0 = __float_as_uint(Bs[buf][krA * BN + SW(krA, nc)]);
                uint32_t b1 = __float_as_uint(Bs[buf][krB * BN + SW(krB, nc)]);
                #pragma unroll
                for (int f = 0; f < FM; ++f)
                    mma_16x8x8(acc[f][nf], a[f], b0, b1);
            }
        }
    };

    const int kTiles = K / BK;
    ldA(0); ldB(0);
    stA(0); stB(0);
    __syncthreads();

    for (int t = 0; t < kTiles; ++t) {
        if (t + 1 < kTiles) { ldA((t + 1) * BK); ldB((t + 1) * BK); }
        compute(t & 1);
        if (t + 1 < kTiles) {
            stA((t + 1) & 1); stB((t + 1) & 1);
            __syncthreads();
        }
    }

    // ---- epilogue ----
    #pragma unroll
    for (int f = 0; f < FM; ++f) {
        int r0 = m0 + mbase + f * 16 + lg;
        #pragma unroll
        for (int nf = 0; nf < 8; ++nf) {
            int cb = n0 + nbase + nf * 8 + 2 * lt;
            #pragma unroll
            for (int rr = 0; rr < 2; ++rr) {
                int m = r0 + rr * 8;
                if (m >= M) continue;
                float bval = bias ? bias[m] : 0.f;
                #pragma unroll
                for (int cc = 0; cc < 2; ++cc) {
                    int n = cb + cc;
                    if (n >= N) continue;
                    float v = acc[f][nf][rr * 2 + cc] + bval;
                    size_t idx = ((size_t)bz * M + m) * N + n;
                    if (mul) v *= mul[idx];
                    Y[idx] = v;
                }
            }
        }
    }
}

// ---------------------------------------------------------------------------
// grouped 3x3 conv, smem-tiled: block = (32x32 tile, group, batch)
// ---------------------------------------------------------------------------
__global__ __launch_bounds__(256)
void dwconv2_kernel(const float* __restrict__ X,
                    const float* __restrict__ W,
                    float* __restrict__ Y)
{
    __shared__ float xs[2][34][35];
    __shared__ float ws[36];

    const int tile = blockIdx.x;          // 0..8
    const int g    = blockIdx.y;          // 0..191
    const int b    = blockIdx.z;
    const int ty0  = (tile / 3) * 32;
    const int tx0  = (tile % 3) * 32;
    const int tid  = threadIdx.x;

    if (tid < 36) ws[tid] = W[(size_t)g * 36 + tid];

    for (int e = tid; e < 2 * 34 * 34; e += 256) {
        int c  = e / (34 * 34);
        int r  = e - c * 34 * 34;
        int yy = r / 34, xx = r - yy * 34;
        int gy = ty0 + yy - 1, gx = tx0 + xx - 1;
        float v = 0.f;
        if (gy >= 0 && gy < Hh && gx >= 0 && gx < Ww)
            v = X[((size_t)b * C2 + 2 * g + c) * HW + gy * Ww + gx];
        xs[c][yy][xx] = v;
    }
    __syncthreads();

    const int x  = tid & 31;
    const int yb = (tid >> 5) * 4;
    #pragma unroll
    for (int j = 0; j < 4; ++j) {
        int y = yb + j;
        float a0 = 0.f, a1 = 0.f;
        #pragma unroll
        for (int c = 0; c < 2; ++c)
            #pragma unroll
            for (int ky = 0; ky < 3; ++ky)
                #pragma unroll
                for (int kx = 0; kx < 3; ++kx) {
                    float v = xs[c][y + ky][x + kx];
                    a0 += v * ws[c * 9 + ky * 3 + kx];
                    a1 += v * ws[18 + c * 9 + ky * 3 + kx];
                }
        size_t o = ((size_t)b * C2 + 2 * g) * HW + (ty0 + y) * Ww + tx0 + x;
        Y[o]      = a0;
        Y[o + HW] = a1;
    }
}

// cat = [q ; y]
__global__ void cat_kernel(const float* __restrict__ QKV,
                           const float* __restrict__ Yin,
                           float* __restrict__ CAT)
{
    int idx = blockIdx.x * blockDim.x + threadIdx.x;
    if (idx >= Bn * C2 * HW) return;
    int p = idx % HW;
    int c = (idx / HW) % C2;
    int b = idx / (HW * C2);
    float v;
    if (c < Cc) v = QKV[((size_t)b * C2 + c) * HW + p];
    else        v = Yin[((size_t)b * Cc + (c - Cc)) * HW + p];
    CAT[idx] = v;
}

// 2x2 avg pool, 96 -> 48
__global__ void pool_kernel(const float* __restrict__ X, float* __restrict__ Y)
{
    int idx = blockIdx.x * blockDim.x + threadIdx.x;
    const int OHW = 48 * 48;
    if (idx >= Bn * C2 * OHW) return;
    int p  = idx % OHW;
    int bc = idx / OHW;
    int y = p / 48, x = p % 48;
    const float* xp = X + (size_t)bc * HW;
    float s = xp[(2 * y) * Ww + 2 * x] + xp[(2 * y) * Ww + 2 * x + 1]
            + xp[(2 * y + 1) * Ww + 2 * x] + xp[(2 * y + 1) * Ww + 2 * x + 1];
    Y[idx] = s * 0.25f;
}

// sig = sigmoid(cat + nearest_resize(k2out 46x46 -> 96x96))
__global__ void sig_kernel(const float* __restrict__ CAT,
                           const float* __restrict__ K2,
                           float* __restrict__ SIG)
{
    int idx = blockIdx.x * blockDim.x + threadIdx.x;
    if (idx >= Bn * C2 * HW) return;
    int p  = idx % HW;
    int bc = idx / HW;
    int y = p / Ww, x = p % Ww;
    int iy = (y * 46) / 96;
    int ix = (x * 46) / 96;
    float s = CAT[idx] + K2[(size_t)bc * (46 * 46) + iy * 46 + ix];
    SIG[idx] = 1.f / (1.f + expf(-s));
}

// ---------------------------------------------------------------------------
// fused deformable conv (groups=8, cg=24, 3x3)
// ---------------------------------------------------------------------------
__global__ __launch_bounds__(128)
void deform_kernel(const float* __restrict__ Q,
                   const float* __restrict__ OFF,
                   const float* __restrict__ W,
                   const float* __restrict__ Bias,
                   float* __restrict__ Y)
{
    __shared__ float ws[24 * 216];
    const int g = blockIdx.y;
    const int b = blockIdx.z;
    const int tid = threadIdx.x;

    for (int e = tid; e < 24 * 216; e += 128) {
        int o = e / 216, r = e - o * 216;
        ws[e] = W[(size_t)(g * CG + o) * 216 + r];
    }
    __syncthreads();

    int p = blockIdx.x * 128 + tid;
    int y = p / Ww, x = p % Ww;
    const float* offb = OFF + (size_t)b * 18 * HW;

    float acc[24];
    #pragma unroll
    for (int o = 0; o < 24; ++o) acc[o] = Bias[g * CG + o];

    const float* qc = Q + ((size_t)b * C2 + g * CG) * HW;

    for (int t = 0; t < 9; ++t) {
        float dy = offb[(size_t)(2 * t) * HW + p];
        float dx = offb[(size_t)(2 * t + 1) * HW + p];
        float m  = 1.f / (1.f + expf(-offb[(size_t)t * HW + p]));
        float py = dy + (float)(y - 1 + t / 3);
        float px = dx + (float)(x - 1 + t % 3);
        float y0f = floorf(py), x0f = floorf(px);
        int   y0 = (int)y0f,    x0 = (int)x0f;
        float fy = py - y0f,    fx = px - x0f;
        float w00 = (1.f - fy) * (1.f - fx);
        float w01 = (1.f - fy) * fx;
        float w10 = fy * (1.f - fx);
        float w11 = fy * fx;
        bool vy0 = (y0 >= 0 && y0 <= Hh - 1), vy1 = (y0 + 1 >= 0 && y0 + 1 <= Hh - 1);
        bool vx0 = (x0 >= 0 && x0 <= Ww - 1), vx1 = (x0 + 1 >= 0 && x0 + 1 <= Ww - 1);
        int cy0 = min(max(y0, 0), Hh - 1),     cy1 = min(max(y0 + 1, 0), Hh - 1);
        int cx0 = min(max(x0, 0), Ww - 1),     cx1 = min(max(x0 + 1, 0), Ww - 1);
        int i00 = cy0 * Ww + cx0, i01 = cy0 * Ww + cx1;
        int i10 = cy1 * Ww + cx0, i11 = cy1 * Ww + cx1;
        w00 = (vy0 && vx0) ? w00 * m : 0.f;
        w01 = (vy0 && vx1) ? w01 * m : 0.f;
        w10 = (vy1 && vx0) ? w10 * m : 0.f;
        w11 = (vy1 && vx1) ? w11 * m : 0.f;

        #pragma unroll
        for (int i = 0; i < 24; ++i) {
            const float* qp = qc + (size_t)i * HW;
            float val = w00 * qp[i00] + w01 * qp[i01] + w10 * qp[i10] + w11 * qp[i11];
            const float* wr = &ws[i * 9 + t];
            #pragma unroll
            for (int o = 0; o < 24; ++o) acc[o] += val * wr[o * 216];
        }
    }
    #pragma unroll
    for (int o = 0; o < 24; ++o)
        Y[((size_t)b * Cc + g * CG + o) * HW + p] = acc[o];
}

// ---------------------------------------------------------------------------
// row L2 norms
// ---------------------------------------------------------------------------
__global__ void rownorm_kernel(const float* __restrict__ QKV,
                               const float* __restrict__ Kb,
                               float* __restrict__ QN,
                               float* __restrict__ KN)
{
    int row   = blockIdx.x;
    int which = row / (Bn * Cc);
    row %= (Bn * Cc);
    int b = row / Cc, c = row % Cc;
    const float* src = which ? (Kb + ((size_t)b * Cc + c) * HW)
                             : (QKV + ((size_t)b * C2 + c) * HW);
    float s = 0.f;
    for (int n = threadIdx.x; n < HW; n += 256) {
        float v = src[n];
        s += v * v;
    }
    __shared__ float sm[256];
    sm[threadIdx.x] = s;
    __syncthreads();
    for (int d = 128; d > 0; d >>= 1) {
        if (threadIdx.x < d) sm[threadIdx.x] += sm[threadIdx.x + d];
        __syncthreads();
    }
    if (threadIdx.x == 0) {
        float nrm = fmaxf(sqrtf(sm[0]), 1e-12f);
        (which ? KN : QN)[b * Cc + c] = nrm;
    }
}

// ---------------------------------------------------------------------------
// attention v2: one block per (b,h).  K-head staged through smem.
// 8 warps: warp w owns q rows 3w..3w+2.
// ---------------------------------------------------------------------------
#define CNK 384
__global__ __launch_bounds__(256)
void attn2_kernel(const float* __restrict__ QKV,
                  const float* __restrict__ Kb,
                  const float* __restrict__ QN,
                  const float* __restrict__ KN,
                  const float* __restrict__ TEMP,
                  float* __restrict__ ATTN)
{
    __shared__ float ks_[24][CNK + 8];
    __shared__ float logits[24][24];

    const int b = blockIdx.x >> 3;
    const int h = blockIdx.x & 7;
    const int tid  = threadIdx.x;
    const int wid  = tid >> 5;
    const int lane = tid & 31;

    const float* qh = QKV + ((size_t)b * C2 + h * HD) * HW;
    const float* kh = Kb  + ((size_t)b * Cc + h * HD) * HW;

    float acc[3][24];
    #pragma unroll
    for (int r = 0; r < 3; ++r)
        #pragma unroll
        for (int j = 0; j < 24; ++j) acc[r][j] = 0.f;

    const float* q0p = qh + (size_t)(3 * wid + 0) * HW;
    const float* q1p = qh + (size_t)(3 * wid + 1) * HW;
    const float* q2p = qh + (size_t)(3 * wid + 2) * HW;

    for (int n0 = 0; n0 < HW; n0 += CNK) {
        __syncthreads();
        for (int e = tid; e < 24 * (CNK / 4); e += 256) {
            int j = e / (CNK / 4);
            int c = e - j * (CNK / 4);
            float4 v = *reinterpret_cast<const float4*>(kh + (size_t)j * HW + n0 + c * 4);
            ks_[j][c * 4 + 0] = v.x;
            ks_[j][c * 4 + 1] = v.y;
            ks_[j][c * 4 + 2] = v.z;
            ks_[j][c * 4 + 3] = v.w;
        }
        __syncthreads();

        for (int i = lane; i < CNK; i += 32) {
            int n = n0 + i;
            float q0 = q0p[n], q1 = q1p[n], q2 = q2p[n];
            #pragma unroll
            for (int j = 0; j < 24; ++j) {
                float kv = ks_[j][i];
                acc[0][j] += q0 * kv;
                acc[1][j] += q1 * kv;
                acc[2][j] += q2 * kv;
            }
        }
    }

    #pragma unroll
    for (int r = 0; r < 3; ++r)
        #pragma unroll
        for (int j = 0; j < 24; ++j) {
            float v = acc[r][j];
            for (int o = 16; o > 0; o >>= 1) v += __shfl_down_sync(0xffffffffu, v, o);
            if (lane == 0) logits[wid * 3 + r][j] = v;
        }
    __syncthreads();

    if (tid < 24) {
        int i = tid;
        float qn = QN[b * Cc + h * HD + i];
        float tp = TEMP[h];
        float s[24];
        float mx = -1e30f;
        #pragma unroll
        for (int j = 0; j < 24; ++j) {
            s[j] = logits[i][j] / (qn * KN[b * Cc + h * HD + j]) * tp;
            mx = fmaxf(mx, s[j]);
        }
        float sum = 0.f;
        #pragma unroll
        for (int j = 0; j < 24; ++j) { s[j] = expf(s[j] - mx); sum += s[j]; }
        float inv = 1.f / sum;
        #pragma unroll
        for (int j = 0; j < 24; ++j)
            ATTN[(((size_t)b * NH + h) * HD + i) * HD + j] = s[j] * inv;
    }
}

// out = attn @ v
__global__ void attnv_kernel(const float* __restrict__ ATTN,
                             const float* __restrict__ QKV,
                             float* __restrict__ AO)
{
    int h = blockIdx.y, b = blockIdx.z;
    int n = blockIdx.x * 256 + threadIdx.x;
    __shared__ float a_s[HD * HD];
    for (int e = threadIdx.x; e < HD * HD; e += 256)
        a_s[e] = ATTN[((size_t)b * NH + h) * HD * HD + e];
    __syncthreads();
    const float* vb = QKV + ((size_t)b * C2 + Cc + h * HD) * HW;
    float acc[HD] = {};
    #pragma unroll
    for (int j = 0; j < HD; ++j) {
        float vv = vb[(size_t)j * HW + n];
        #pragma unroll
        for (int i = 0; i < HD; ++i) acc[i] += a_s[i * HD + j] * vv;
    }
    #pragma unroll
    for (int i = 0; i < HD; ++i)
        AO[((size_t)b * Cc + h * HD + i) * HW + n] = acc[i];
}

// ---------------------------------------------------------------------------
// launcher
// ---------------------------------------------------------------------------
extern "C" void kernel_launch(void* const* d_in, const int* in_sizes, int n_in,
                              void* d_out, int out_size)
{
    const float* x           = (const float*)d_in[0];
    const float* y           = (const float*)d_in[1];
    const float* temperature = (const float*)d_in[2];
    const float* qkv_w       = (const float*)d_in[3];
    const float* qkv_conv_w  = (const float*)d_in[4];
    const float* proj_w      = (const float*)d_in[5];
    const float* k2_w        = (const float*)d_in[6];
    const float* k3_w        = (const float*)d_in[7];
    const float* k4_w        = (const float*)d_in[8];
    const float* deform_w    = (const float*)d_in[9];
    const float* deform_b    = (const float*)d_in[10];
    const float* pw_w        = (const float*)d_in[11];
    const float* pw_b        = (const float*)d_in[12];
    float* out = (float*)d_out;

    float* S = nullptr;
    cudaGetSymbolAddress((void**)&S, g_scratch);
    float* QKV1 = S + OFF_QKV1;
    float* QKV  = S + OFF_QKV;
    float* CAT  = S + OFF_CAT;
    float* SIG  = S + OFF_SIG;
    float* SC   = S + OFF_SC;
    float* POOL = S + OFF_POOL;
    float* K2   = S + OFF_K2;
    float* OFFb = S + OFF_OFF;
    float* FEAT = S + OFF_FEAT;
    float* Kb   = S + OFF_K;
    float* AO   = S + OFF_AO;
    float* QN   = S + OFF_QN;
    float* KN   = S + OFF_KN;
    float* ATTN = S + OFF_ATTN;

    const int NE = Bn * C2 * HW;

    // 1) qkv 1x1: 384 x 192 x 9216
    conv_mma2<1, 4><<<dim3(HW / 256, C2 / 128, Bn), 256>>>(
        qkv_w, x, QKV1, nullptr, nullptr, C2, Cc, Hh, Ww, Hh, Ww, 0, 0);
    // 2) grouped 3x3 (groups=192), smem tiled
    dwconv2_kernel<<<dim3(9, 192, Bn), 256>>>(QKV1, qkv_conv_w, QKV);
    // 3) cat = [q ; y]
    cat_kernel<<<(NE + 255) / 256, 256>>>(QKV, y, CAT);
    // 4) avg pool 2x2
    pool_kernel<<<(Bn * C2 * 48 * 48 + 255) / 256, 256>>>(CAT, POOL);
    // 5) k2 conv 3x3 pad=0 : 48x48 -> 46x46
    conv_mma2<3, 4><<<dim3((46 * 46 + 255) / 256, C2 / 128, Bn), 256>>>(
        k2_w, POOL, K2, nullptr, nullptr, C2, C2, 48, 48, 46, 46, 0, 0);
    // 6) sig = sigmoid(cat + upsample(k2))
    sig_kernel<<<(NE + 255) / 256, 256>>>(CAT, K2, SIG);
    // 7) sc = conv3x3(cat, k3, pad=1) * sig
    conv_mma2<3, 4><<<dim3(HW / 256, C2 / 128, Bn), 256>>>(
        k3_w, CAT, SC, nullptr, SIG, C2, C2, Hh, Ww, Hh, Ww, 1, 0);
    // 8) offset = conv3x3(sc, k4, pad=1), M=18 (BM=32 variant)
    conv_mma2<3, 1><<<dim3(HW / 256, 1, Bn), 256>>>(
        k4_w, SC, OFFb, nullptr, nullptr, 18, C2, Hh, Ww, Hh, Ww, 1, 0);
    // 9) deformable conv -> feat
    deform_kernel<<<dim3(HW / 128, Gg, Bn), 128>>>(QKV, OFFb, deform_w, deform_b, FEAT);
    // 10) k = 1x1(relu(feat)) + pw_b
    conv_mma2<1, 4><<<dim3(HW / 256, (Cc + 127) / 128, Bn), 256>>>(
        pw_w, FEAT, Kb, pw_b, nullptr, Cc, Cc, Hh, Ww, Hh, Ww, 0, 1);
    // 11) row norms
    rownorm_kernel<<<2 * Bn * Cc, 256>>>(QKV, Kb, QN, KN);
    // 12) attention logits + softmax
    attn2_kernel<<<Bn * NH, 256>>>(QKV, Kb, QN, KN, temperature, ATTN);
    // 13) out = attn @ v
    attnv_kernel<<<dim3(HW / 256, NH, Bn), 256>>>(ATTN, QKV, AO);
    // 14) final 1x1 proj -> d_out
    conv_mma2<1, 4><<<dim3(HW / 256, (Cc + 127) / 128, Bn), 256>>>(
        proj_w, AO, out, nullptr, nullptr, Cc, Cc, Hh, Ww, Hh, Ww, 0, 0);
}

// round 4
// speedup vs baseline: 1.3680x; 1.3680x over previous
#include <cuda_runtime.h>
#include <math.h>
#include <stdint.h>

// ---------------------------------------------------------------------------
// Problem constants
// ---------------------------------------------------------------------------
#define Bn   4
#define Cc   192
#define C2   384
#define Hh   96
#define Ww   96
#define HW   (Hh*Ww)          // 9216
#define NH   8
#define HD   24
#define Gg   8
#define CG   24

// scratch offsets (floats)
#define OFF_QKV1  0ul
#define OFF_QKV   14155776ul
#define OFF_CAT   28311552ul
#define OFF_SC    42467328ul
#define OFF_POOL  56623104ul
#define OFF_K2    60162048ul
#define OFF_OFF   63412224ul
#define OFF_FEAT  64075776ul
#define OFF_K     71153664ul
#define OFF_AO    78231552ul
#define OFF_QN    85309440ul
#define OFF_KN    85310208ul
#define OFF_ATTN  85310976ul
#define SCRATCH_TOTAL 85329408ul

__device__ float g_scratch[SCRATCH_TOTAL];

// ---------------------------------------------------------------------------
// tf32 helpers
// ---------------------------------------------------------------------------
__device__ __forceinline__ float f2tf32(float x) {
    uint32_t u;
    asm("cvt.rna.tf32.f32 %0, %1;" : "=r"(u) : "f"(x));
    return __uint_as_float(u);
}

__device__ __forceinline__ void mma_16x8x8(float* c, const uint32_t* a,
                                           uint32_t b0, uint32_t b1) {
    asm volatile(
        "mma.sync.aligned.m16n8k8.row.col.f32.tf32.tf32.f32 "
        "{%0,%1,%2,%3}, {%4,%5,%6,%7}, {%8,%9}, {%0,%1,%2,%3};\n"
        : "+f"(c[0]), "+f"(c[1]), "+f"(c[2]), "+f"(c[3])
        : "r"(a[0]), "r"(a[1]), "r"(a[2]), "r"(a[3]), "r"(b0), "r"(b1));
}

// ---------------------------------------------------------------------------
// tf32 tensor-core implicit-GEMM conv (round-2 proven config).
// BM = 32*FM, BN = 128, BK = 16, 256 threads = 8 warps (2M x 4N),
// warp tile (16*FM) x 32.  Double-buffered padded smem.
// ---------------------------------------------------------------------------
template<int KS, int FM>
__global__ __launch_bounds__(256)
void conv_mma(const float* __restrict__ Wt,
              const float* __restrict__ X,
              float* __restrict__ Y,
              const float* __restrict__ bias,
              const float* __restrict__ mul,
              int M, int Cin, int IH, int IW,
              int OH, int OW, int pad, int relu_in)
{
    constexpr int BM   = 32 * FM;
    constexpr int BN   = 128;
    constexpr int BK   = 16;
    constexpr int ASTR = BM + 8;
    constexpr int BSTR = BN + 8;
    constexpr int AELE = BM * BK / 4;
    constexpr int AITER = (AELE + 255) / 256;

    __shared__ float As[2][BK * ASTR];
    __shared__ float Bs[2][BK * BSTR];

    const int N  = OH * OW;
    const int K  = Cin * KS * KS;
    const int bz = blockIdx.z;
    const int m0 = blockIdx.y * BM;
    const int n0 = blockIdx.x * BN;

    const int tid  = threadIdx.x;
    const int wid  = tid >> 5;
    const int lane = tid & 31;
    const int wm   = wid & 1;
    const int wn   = wid >> 1;
    const int mbase = wm * (16 * FM);
    const int nbase = wn * 32;
    const int lg = lane >> 2;
    const int lt = lane & 3;

    const float* Xb = X + (size_t)bz * Cin * IH * IW;

    float acc[FM][4][4];
    #pragma unroll
    for (int f = 0; f < FM; ++f)
        #pragma unroll
        for (int nf = 0; nf < 4; ++nf)
            #pragma unroll
            for (int r = 0; r < 4; ++r) acc[f][nf][r] = 0.f;

    const int bn = tid & 127;
    const int gn = n0 + bn;
    const bool nvalid = gn < N;
    int oy = 0, ox = 0;
    if (KS == 3 && nvalid) { oy = gn / OW; ox = gn - oy * OW; }

    float4 aReg[AITER];
    float  bReg[8];

    auto ldA = [&](int k0) {
        #pragma unroll
        for (int r = 0; r < AITER; ++r) {
            int e = tid + r * 256;
            float4 v = make_float4(0.f, 0.f, 0.f, 0.f);
            if (AELE == 512 || e < AELE) {
                int m  = e >> 2;
                int kq = e & 3;
                int gm = m0 + m;
                if (gm < M)
                    v = *reinterpret_cast<const float4*>(Wt + (size_t)gm * K + k0 + kq * 4);
            }
            aReg[r] = v;
        }
    };
    auto stA = [&](int buf) {
        #pragma unroll
        for (int r = 0; r < AITER; ++r) {
            int e = tid + r * 256;
            if (AELE == 512 || e < AELE) {
                int m  = e >> 2;
                int kq = e & 3;
                float* p = &As[buf][(kq * 4) * ASTR + m];
                p[0 * ASTR] = f2tf32(aReg[r].x);
                p[1 * ASTR] = f2tf32(aReg[r].y);
                p[2 * ASTR] = f2tf32(aReg[r].z);
                p[3 * ASTR] = f2tf32(aReg[r].w);
            }
        }
    };
    auto ldB = [&](int k0) {
        #pragma unroll
        for (int r = 0; r < 8; ++r) {
            int k  = (tid >> 7) + 2 * r;
            int gk = k0 + k;
            float v = 0.f;
            if (nvalid) {
                if (KS == 1) {
                    v = Xb[(size_t)gk * N + gn];
                } else {
                    int ic = gk / 9;
                    int t  = gk - ic * 9;
                    int iy = oy + t / 3 - pad;
                    int ix = ox + (t % 3) - pad;
                    if (iy >= 0 && iy < IH && ix >= 0 && ix < IW)
                        v = Xb[((size_t)ic * IH + iy) * IW + ix];
                }
                if (relu_in) v = fmaxf(v, 0.f);
            }
            bReg[r] = v;
        }
    };
    auto stB = [&](int buf) {
        #pragma unroll
        for (int r = 0; r < 8; ++r) {
            int k = (tid >> 7) + 2 * r;
            Bs[buf][k * BSTR + bn] = f2tf32(bReg[r]);
        }
    };
    auto compute = [&](int buf) {
        #pragma unroll
        for (int ks = 0; ks < 2; ++ks) {
            const int kr = ks * 8 + lt;
            uint32_t a[FM][4];
            #pragma unroll
            for (int f = 0; f < FM; ++f) {
                int mr = mbase + f * 16 + lg;
                a[f][0] = __float_as_uint(As[buf][kr * ASTR + mr]);
                a[f][1] = __float_as_uint(As[buf][kr * ASTR + mr + 8]);
                a[f][2] = __float_as_uint(As[buf][(kr + 4) * ASTR + mr]);
                a[f][3] = __float_as_uint(As[buf][(kr + 4) * ASTR + mr + 8]);
            }
            #pragma unroll
            for (int nf = 0; nf < 4; ++nf) {
                int nc = nbase + nf * 8 + lg;
                uint32_t b0 = __float_as_uint(Bs[buf][kr * BSTR + nc]);
                uint32_t b1 = __float_as_uint(Bs[buf][(kr + 4) * BSTR + nc]);
                #pragma unroll
                for (int f = 0; f < FM; ++f)
                    mma_16x8x8(acc[f][nf], a[f], b0, b1);
            }
        }
    };

    const int kTiles = K / BK;
    ldA(0); ldB(0);
    stA(0); stB(0);
    __syncthreads();

    for (int t = 0; t < kTiles; ++t) {
        if (t + 1 < kTiles) { ldA((t + 1) * BK); ldB((t + 1) * BK); }
        compute(t & 1);
        if (t + 1 < kTiles) {
            stA((t + 1) & 1); stB((t + 1) & 1);
            __syncthreads();
        }
    }

    // ---- epilogue ----
    #pragma unroll
    for (int f = 0; f < FM; ++f) {
        int r0 = m0 + mbase + f * 16 + lg;
        #pragma unroll
        for (int nf = 0; nf < 4; ++nf) {
            int cb = n0 + nbase + nf * 8 + 2 * lt;
            #pragma unroll
            for (int rr = 0; rr < 2; ++rr) {
                int m = r0 + rr * 8;
                if (m >= M) continue;
                float bval = bias ? bias[m] : 0.f;
                #pragma unroll
                for (int cc = 0; cc < 2; ++cc) {
                    int n = cb + cc;
                    if (n >= N) continue;
                    float v = acc[f][nf][rr * 2 + cc] + bval;
                    size_t idx = ((size_t)bz * M + m) * N + n;
                    if (mul) v *= mul[idx];
                    Y[idx] = v;
                }
            }
        }
    }
}

// ---------------------------------------------------------------------------
// grouped 3x3 conv, smem-tiled: block = (32x32 tile, group, batch)
// ---------------------------------------------------------------------------
__global__ __launch_bounds__(256)
void dwconv2_kernel(const float* __restrict__ X,
                    const float* __restrict__ W,
                    float* __restrict__ Y)
{
    __shared__ float xs[2][34][35];
    __shared__ float ws[36];

    const int tile = blockIdx.x;
    const int g    = blockIdx.y;
    const int b    = blockIdx.z;
    const int ty0  = (tile / 3) * 32;
    const int tx0  = (tile % 3) * 32;
    const int tid  = threadIdx.x;

    if (tid < 36) ws[tid] = W[(size_t)g * 36 + tid];

    for (int e = tid; e < 2 * 34 * 34; e += 256) {
        int c  = e / (34 * 34);
        int r  = e - c * 34 * 34;
        int yy = r / 34, xx = r - yy * 34;
        int gy = ty0 + yy - 1, gx = tx0 + xx - 1;
        float v = 0.f;
        if (gy >= 0 && gy < Hh && gx >= 0 && gx < Ww)
            v = X[((size_t)b * C2 + 2 * g + c) * HW + gy * Ww + gx];
        xs[c][yy][xx] = v;
    }
    __syncthreads();

    const int x  = tid & 31;
    const int yb = (tid >> 5) * 4;
    #pragma unroll
    for (int j = 0; j < 4; ++j) {
        int y = yb + j;
        float a0 = 0.f, a1 = 0.f;
        #pragma unroll
        for (int c = 0; c < 2; ++c)
            #pragma unroll
            for (int ky = 0; ky < 3; ++ky)
                #pragma unroll
                for (int kx = 0; kx < 3; ++kx) {
                    float v = xs[c][y + ky][x + kx];
                    a0 += v * ws[c * 9 + ky * 3 + kx];
                    a1 += v * ws[18 + c * 9 + ky * 3 + kx];
                }
        size_t o = ((size_t)b * C2 + 2 * g) * HW + (ty0 + y) * Ww + tx0 + x;
        Y[o]      = a0;
        Y[o + HW] = a1;
    }
}

// cat = [q ; y]
__global__ void cat_kernel(const float* __restrict__ QKV,
                           const float* __restrict__ Yin,
                           float* __restrict__ CAT)
{
    int idx = blockIdx.x * blockDim.x + threadIdx.x;
    if (idx >= Bn * C2 * HW) return;
    int p = idx % HW;
    int c = (idx / HW) % C2;
    int b = idx / (HW * C2);
    float v;
    if (c < Cc) v = QKV[((size_t)b * C2 + c) * HW + p];
    else        v = Yin[((size_t)b * Cc + (c - Cc)) * HW + p];
    CAT[idx] = v;
}

// 2x2 avg pool, 96 -> 48
__global__ void pool_kernel(const float* __restrict__ X, float* __restrict__ Y)
{
    int idx = blockIdx.x * blockDim.x + threadIdx.x;
    const int OHW = 48 * 48;
    if (idx >= Bn * C2 * OHW) return;
    int p  = idx % OHW;
    int bc = idx / OHW;
    int y = p / 48, x = p % 48;
    const float* xp = X + (size_t)bc * HW;
    float s = xp[(2 * y) * Ww + 2 * x] + xp[(2 * y) * Ww + 2 * x + 1]
            + xp[(2 * y + 1) * Ww + 2 * x] + xp[(2 * y + 1) * Ww + 2 * x + 1];
    Y[idx] = s * 0.25f;
}

// SC *= sigmoid(CAT + nearest_resize(K2 46x46 -> 96x96))
__global__ void sigmul_kernel(float* __restrict__ SC,
                              const float* __restrict__ CAT,
                              const float* __restrict__ K2)
{
    int idx = blockIdx.x * blockDim.x + threadIdx.x;
    if (idx >= Bn * C2 * HW) return;
    int p  = idx % HW;
    int bc = idx / HW;
    int y = p / Ww, x = p % Ww;
    int iy = (y * 46) / 96;
    int ix = (x * 46) / 96;
    float s = CAT[idx] + K2[(size_t)bc * (46 * 46) + iy * 46 + ix];
    SC[idx] *= 1.f / (1.f + expf(-s));
}

// ---------------------------------------------------------------------------
// fused deformable conv (groups=8, cg=24, 3x3)
// ---------------------------------------------------------------------------
__global__ __launch_bounds__(128)
void deform_kernel(const float* __restrict__ Q,
                   const float* __restrict__ OFF,
                   const float* __restrict__ W,
                   const float* __restrict__ Bias,
                   float* __restrict__ Y)
{
    __shared__ float ws[24 * 216];
    const int g = blockIdx.y;
    const int b = blockIdx.z;
    const int tid = threadIdx.x;

    for (int e = tid; e < 24 * 216; e += 128) {
        int o = e / 216, r = e - o * 216;
        ws[e] = W[(size_t)(g * CG + o) * 216 + r];
    }
    __syncthreads();

    int p = blockIdx.x * 128 + tid;
    int y = p / Ww, x = p % Ww;
    const float* offb = OFF + (size_t)b * 18 * HW;

    float acc[24];
    #pragma unroll
    for (int o = 0; o < 24; ++o) acc[o] = Bias[g * CG + o];

    const float* qc = Q + ((size_t)b * C2 + g * CG) * HW;

    for (int t = 0; t < 9; ++t) {
        float dy = offb[(size_t)(2 * t) * HW + p];
        float dx = offb[(size_t)(2 * t + 1) * HW + p];
        float m  = 1.f / (1.f + expf(-offb[(size_t)t * HW + p]));
        float py = dy + (float)(y - 1 + t / 3);
        float px = dx + (float)(x - 1 + t % 3);
        float y0f = floorf(py), x0f = floorf(px);
        int   y0 = (int)y0f,    x0 = (int)x0f;
        float fy = py - y0f,    fx = px - x0f;
        float w00 = (1.f - fy) * (1.f - fx);
        float w01 = (1.f - fy) * fx;
        float w10 = fy * (1.f - fx);
        float w11 = fy * fx;
        bool vy0 = (y0 >= 0 && y0 <= Hh - 1), vy1 = (y0 + 1 >= 0 && y0 + 1 <= Hh - 1);
        bool vx0 = (x0 >= 0 && x0 <= Ww - 1), vx1 = (x0 + 1 >= 0 && x0 + 1 <= Ww - 1);
        int cy0 = min(max(y0, 0), Hh - 1),     cy1 = min(max(y0 + 1, 0), Hh - 1);
        int cx0 = min(max(x0, 0), Ww - 1),     cx1 = min(max(x0 + 1, 0), Ww - 1);
        int i00 = cy0 * Ww + cx0, i01 = cy0 * Ww + cx1;
        int i10 = cy1 * Ww + cx0, i11 = cy1 * Ww + cx1;
        w00 = (vy0 && vx0) ? w00 * m : 0.f;
        w01 = (vy0 && vx1) ? w01 * m : 0.f;
        w10 = (vy1 && vx0) ? w10 * m : 0.f;
        w11 = (vy1 && vx1) ? w11 * m : 0.f;

        #pragma unroll
        for (int i = 0; i < 24; ++i) {
            const float* qp = qc + (size_t)i * HW;
            float val = w00 * qp[i00] + w01 * qp[i01] + w10 * qp[i10] + w11 * qp[i11];
            const float* wr = &ws[i * 9 + t];
            #pragma unroll
            for (int o = 0; o < 24; ++o) acc[o] += val * wr[o * 216];
        }
    }
    #pragma unroll
    for (int o = 0; o < 24; ++o)
        Y[((size_t)b * Cc + g * CG + o) * HW + p] = acc[o];
}

// ---------------------------------------------------------------------------
// row L2 norms
// ---------------------------------------------------------------------------
__global__ void rownorm_kernel(const float* __restrict__ QKV,
                               const float* __restrict__ Kb,
                               float* __restrict__ QN,
                               float* __restrict__ KN)
{
    int row   = blockIdx.x;
    int which = row / (Bn * Cc);
    row %= (Bn * Cc);
    int b = row / Cc, c = row % Cc;
    const float* src = which ? (Kb + ((size_t)b * Cc + c) * HW)
                             : (QKV + ((size_t)b * C2 + c) * HW);
    float s = 0.f;
    for (int n = threadIdx.x; n < HW; n += 256) {
        float v = src[n];
        s += v * v;
    }
    __shared__ float sm[256];
    sm[threadIdx.x] = s;
    __syncthreads();
    for (int d = 128; d > 0; d >>= 1) {
        if (threadIdx.x < d) sm[threadIdx.x] += sm[threadIdx.x + d];
        __syncthreads();
    }
    if (threadIdx.x == 0) {
        float nrm = fmaxf(sqrtf(sm[0]), 1e-12f);
        (which ? KN : QN)[b * Cc + c] = nrm;
    }
}

// ---------------------------------------------------------------------------
// attention: one block per (b,h).  K-head staged through smem.
// ---------------------------------------------------------------------------
#define CNK 384
__global__ __launch_bounds__(256)
void attn2_kernel(const float* __restrict__ QKV,
                  const float* __restrict__ Kb,
                  const float* __restrict__ QN,
                  const float* __restrict__ KN,
                  const float* __restrict__ TEMP,
                  float* __restrict__ ATTN)
{
    __shared__ float ks_[24][CNK + 8];
    __shared__ float logits[24][24];

    const int b = blockIdx.x >> 3;
    const int h = blockIdx.x & 7;
    const int tid  = threadIdx.x;
    const int wid  = tid >> 5;
    const int lane = tid & 31;

    const float* qh = QKV + ((size_t)b * C2 + h * HD) * HW;
    const float* kh = Kb  + ((size_t)b * Cc + h * HD) * HW;

    float acc[3][24];
    #pragma unroll
    for (int r = 0; r < 3; ++r)
        #pragma unroll
        for (int j = 0; j < 24; ++j) acc[r][j] = 0.f;

    const float* q0p = qh + (size_t)(3 * wid + 0) * HW;
    const float* q1p = qh + (size_t)(3 * wid + 1) * HW;
    const float* q2p = qh + (size_t)(3 * wid + 2) * HW;

    for (int n0 = 0; n0 < HW; n0 += CNK) {
        __syncthreads();
        for (int e = tid; e < 24 * (CNK / 4); e += 256) {
            int j = e / (CNK / 4);
            int c = e - j * (CNK / 4);
            float4 v = *reinterpret_cast<const float4*>(kh + (size_t)j * HW + n0 + c * 4);
            ks_[j][c * 4 + 0] = v.x;
            ks_[j][c * 4 + 1] = v.y;
            ks_[j][c * 4 + 2] = v.z;
            ks_[j][c * 4 + 3] = v.w;
        }
        __syncthreads();

        for (int i = lane; i < CNK; i += 32) {
            int n = n0 + i;
            float q0 = q0p[n], q1 = q1p[n], q2 = q2p[n];
            #pragma unroll
            for (int j = 0; j < 24; ++j) {
                float kv = ks_[j][i];
                acc[0][j] += q0 * kv;
                acc[1][j] += q1 * kv;
                acc[2][j] += q2 * kv;
            }
        }
    }

    #pragma unroll
    for (int r = 0; r < 3; ++r)
        #pragma unroll
        for (int j = 0; j < 24; ++j) {
            float v = acc[r][j];
            for (int o = 16; o > 0; o >>= 1) v += __shfl_down_sync(0xffffffffu, v, o);
            if (lane == 0) logits[wid * 3 + r][j] = v;
        }
    __syncthreads();

    if (tid < 24) {
        int i = tid;
        float qn = QN[b * Cc + h * HD + i];
        float tp = TEMP[h];
        float s[24];
        float mx = -1e30f;
        #pragma unroll
        for (int j = 0; j < 24; ++j) {
            s[j] = logits[i][j] / (qn * KN[b * Cc + h * HD + j]) * tp;
            mx = fmaxf(mx, s[j]);
        }
        float sum = 0.f;
        #pragma unroll
        for (int j = 0; j < 24; ++j) { s[j] = expf(s[j] - mx); sum += s[j]; }
        float inv = 1.f / sum;
        #pragma unroll
        for (int j = 0; j < 24; ++j)
            ATTN[(((size_t)b * NH + h) * HD + i) * HD + j] = s[j] * inv;
    }
}

// out = attn @ v
__global__ void attnv_kernel(const float* __restrict__ ATTN,
                             const float* __restrict__ QKV,
                             float* __restrict__ AO)
{
    int h = blockIdx.y, b = blockIdx.z;
    int n = blockIdx.x * 256 + threadIdx.x;
    __shared__ float a_s[HD * HD];
    for (int e = threadIdx.x; e < HD * HD; e += 256)
        a_s[e] = ATTN[((size_t)b * NH + h) * HD * HD + e];
    __syncthreads();
    const float* vb = QKV + ((size_t)b * C2 + Cc + h * HD) * HW;
    float acc[HD] = {};
    #pragma unroll
    for (int j = 0; j < HD; ++j) {
        float vv = vb[(size_t)j * HW + n];
        #pragma unroll
        for (int i = 0; i < HD; ++i) acc[i] += a_s[i * HD + j] * vv;
    }
    #pragma unroll
    for (int i = 0; i < HD; ++i)
        AO[((size_t)b * Cc + h * HD + i) * HW + n] = acc[i];
}

// ---------------------------------------------------------------------------
// launcher
// ---------------------------------------------------------------------------
extern "C" void kernel_launch(void* const* d_in, const int* in_sizes, int n_in,
                              void* d_out, int out_size)
{
    const float* x           = (const float*)d_in[0];
    const float* y           = (const float*)d_in[1];
    const float* temperature = (const float*)d_in[2];
    const float* qkv_w       = (const float*)d_in[3];
    const float* qkv_conv_w  = (const float*)d_in[4];
    const float* proj_w      = (const float*)d_in[5];
    const float* k2_w        = (const float*)d_in[6];
    const float* k3_w        = (const float*)d_in[7];
    const float* k4_w        = (const float*)d_in[8];
    const float* deform_w    = (const float*)d_in[9];
    const float* deform_b    = (const float*)d_in[10];
    const float* pw_w        = (const float*)d_in[11];
    const float* pw_b        = (const float*)d_in[12];
    float* out = (float*)d_out;

    float* S = nullptr;
    cudaGetSymbolAddress((void**)&S, g_scratch);
    float* QKV1 = S + OFF_QKV1;
    float* QKV  = S + OFF_QKV;
    float* CAT  = S + OFF_CAT;
    float* SC   = S + OFF_SC;
    float* POOL = S + OFF_POOL;
    float* K2   = S + OFF_K2;
    float* OFFb = S + OFF_OFF;
    float* FEAT = S + OFF_FEAT;
    float* Kb   = S + OFF_K;
    float* AO   = S + OFF_AO;
    float* QN   = S + OFF_QN;
    float* KN   = S + OFF_KN;
    float* ATTN = S + OFF_ATTN;

    const int NE = Bn * C2 * HW;

    // 1) qkv 1x1: 384 x 192 x 9216
    conv_mma<1, 4><<<dim3(HW / 128, C2 / 128, Bn), 256>>>(
        qkv_w, x, QKV1, nullptr, nullptr, C2, Cc, Hh, Ww, Hh, Ww, 0, 0);
    // 2) grouped 3x3 (groups=192), smem tiled
    dwconv2_kernel<<<dim3(9, 192, Bn), 256>>>(QKV1, qkv_conv_w, QKV);
    // 3) cat = [q ; y]
    cat_kernel<<<(NE + 255) / 256, 256>>>(QKV, y, CAT);
    // 4) k3 conv 3x3 pad=1 (raw; sig multiply applied later) -- in ncu slot
    conv_mma<3, 4><<<dim3(HW / 128, C2 / 128, Bn), 256>>>(
        k3_w, CAT, SC, nullptr, nullptr, C2, C2, Hh, Ww, Hh, Ww, 1, 0);
    // 5) avg pool 2x2
    pool_kernel<<<(Bn * C2 * 48 * 48 + 255) / 256, 256>>>(CAT, POOL);
    // 6) k2 conv 3x3 pad=0 : 48x48 -> 46x46
    conv_mma<3, 4><<<dim3((46 * 46 + 127) / 128, C2 / 128, Bn), 256>>>(
        k2_w, POOL, K2, nullptr, nullptr, C2, C2, 48, 48, 46, 46, 0, 0);
    // 7) SC *= sigmoid(CAT + upsample(K2))
    sigmul_kernel<<<(NE + 255) / 256, 256>>>(SC, CAT, K2);
    // 8) offset = conv3x3(sc, k4, pad=1), M=18 (BM=32 variant)
    conv_mma<3, 1><<<dim3(HW / 128, 1, Bn), 256>>>(
        k4_w, SC, OFFb, nullptr, nullptr, 18, C2, Hh, Ww, Hh, Ww, 1, 0);
    // 9) deformable conv -> feat
    deform_kernel<<<dim3(HW / 128, Gg, Bn), 128>>>(QKV, OFFb, deform_w, deform_b, FEAT);
    // 10) k = 1x1(relu(feat)) + pw_b
    conv_mma<1, 4><<<dim3(HW / 128, (Cc + 127) / 128, Bn), 256>>>(
        pw_w, FEAT, Kb, pw_b, nullptr, Cc, Cc, Hh, Ww, Hh, Ww, 0, 1);
    // 11) row norms
    rownorm_kernel<<<2 * Bn * Cc, 256>>>(QKV, Kb, QN, KN);
    // 12) attention logits + softmax
    attn2_kernel<<<Bn * NH, 256>>>(QKV, Kb, QN, KN, temperature, ATTN);
    // 13) out = attn @ v
    attnv_kernel<<<dim3(HW / 256, NH, Bn), 256>>>(ATTN, QKV, AO);
    // 14) final 1x1 proj -> d_out
    conv_mma<1, 4><<<dim3(HW / 128, (Cc + 127) / 128, Bn), 256>>>(
        proj_w, AO, out, nullptr, nullptr, Cc, Cc, Hh, Ww, Hh, Ww, 0, 0);
}

// round 5
// speedup vs baseline: 1.9071x; 1.3941x over previous
#include <cuda_runtime.h>
#include <math.h>
#include <stdint.h>

// ---------------------------------------------------------------------------
// Problem constants
// ---------------------------------------------------------------------------
#define Bn   4
#define Cc   192
#define C2   384
#define Hh   96
#define Ww   96
#define HW   (Hh*Ww)          // 9216
#define NH   8
#define HD   24
#define Gg   8
#define CG   24

// scratch offsets (floats)
#define OFF_QKV1  0ul
#define OFF_QKV   14155776ul
#define OFF_CAT   28311552ul
#define OFF_SC    42467328ul
#define OFF_POOL  56623104ul
#define OFF_K2    60162048ul
#define OFF_OFF   63412224ul
#define OFF_FEAT  64075776ul
#define OFF_K     71153664ul
#define OFF_AO    78231552ul
#define OFF_QN    85309440ul
#define OFF_KN    85310208ul
#define OFF_ATTN  85310976ul
#define OFF_XT    85329408ul     // 4*192*9216 = 7077888
#define SCRATCH_TOTAL 92407296ul

__device__ float g_scratch[SCRATCH_TOTAL];

// ---------------------------------------------------------------------------
// tf32 / cp.async helpers
// ---------------------------------------------------------------------------
__device__ __forceinline__ float f2tf32(float x) {
    uint32_t u;
    asm("cvt.rna.tf32.f32 %0, %1;" : "=r"(u) : "f"(x));
    return __uint_as_float(u);
}

__device__ __forceinline__ void mma_16x8x8(float* c, const uint32_t* a,
                                           uint32_t b0, uint32_t b1) {
    asm volatile(
        "mma.sync.aligned.m16n8k8.row.col.f32.tf32.tf32.f32 "
        "{%0,%1,%2,%3}, {%4,%5,%6,%7}, {%8,%9}, {%0,%1,%2,%3};\n"
        : "+f"(c[0]), "+f"(c[1]), "+f"(c[2]), "+f"(c[3])
        : "r"(a[0]), "r"(a[1]), "r"(a[2]), "r"(a[3]), "r"(b0), "r"(b1));
}

__device__ __forceinline__ void cpasync4(uint32_t saddr, const float* g, bool pred) {
    int sz = pred ? 4 : 0;
    asm volatile("cp.async.ca.shared.global [%0], [%1], 4, %2;\n"
                 :: "r"(saddr), "l"(g), "r"(sz));
}
__device__ __forceinline__ void cpasync16(uint32_t saddr, const float* g) {
    asm volatile("cp.async.cg.shared.global [%0], [%1], 16;\n"
                 :: "r"(saddr), "l"(g));
}
#define CP_COMMIT() asm volatile("cp.async.commit_group;\n" ::: "memory")
#define CP_WAIT0()  asm volatile("cp.async.wait_group 0;\n" ::: "memory")

// ---------------------------------------------------------------------------
// tf32 tensor-core implicit-GEMM conv, cp.async version.
// BM = 32*FM, BN = 128, BK = 16, 256 threads = 8 warps (2M x 4N).
// B inputs MUST be pre-rounded to tf32 by their producers.
// For KS==1, N must be a multiple of 128 (holds for all 1x1 convs here).
// ---------------------------------------------------------------------------
template<int KS, int FM>
__global__ __launch_bounds__(256)
void conv_mma(const float* __restrict__ Wt,
              const float* __restrict__ X,
              float* __restrict__ Y,
              const float* __restrict__ bias,
              int M, int Cin, int IH, int IW,
              int OH, int OW, int pad)
{
    constexpr int BM   = 32 * FM;
    constexpr int BN   = 128;
    constexpr int BK   = 16;
    constexpr int ASTR = BM + 8;
    constexpr int BSTR = BN + 8;
    constexpr int AELE = BM * BK / 4;
    constexpr int AITER = (AELE + 255) / 256;

    __shared__ float As[2][BK * ASTR];
    __shared__ float Bs[2][BK * BSTR];

    const int N  = OH * OW;
    const int K  = Cin * KS * KS;
    const int bz = blockIdx.z;
    const int m0 = blockIdx.y * BM;
    const int n0 = blockIdx.x * BN;

    const int tid  = threadIdx.x;
    const int wid  = tid >> 5;
    const int lane = tid & 31;
    const int wm   = wid & 1;
    const int wn   = wid >> 1;
    const int mbase = wm * (16 * FM);
    const int nbase = wn * 32;
    const int lg = lane >> 2;
    const int lt = lane & 3;

    const float* Xb = X + (size_t)bz * Cin * IH * IW;

    float acc[FM][4][4];
    #pragma unroll
    for (int f = 0; f < FM; ++f)
        #pragma unroll
        for (int nf = 0; nf < 4; ++nf)
            #pragma unroll
            for (int r = 0; r < 4; ++r) acc[f][nf][r] = 0.f;

    // B-gather per-thread coords (KS==3 path)
    const int bn = tid & 127;
    const int gn = n0 + bn;
    const bool nvalid = gn < N;
    int oy = 0, ox = 0;
    if (KS == 3) { int g = nvalid ? gn : 0; oy = g / OW; ox = g - oy * OW; }

    float4 aReg[AITER];

    auto ldA = [&](int k0) {
        #pragma unroll
        for (int r = 0; r < AITER; ++r) {
            int e = tid + r * 256;
            float4 v = make_float4(0.f, 0.f, 0.f, 0.f);
            if (AELE == 512 || e < AELE) {
                int m  = e >> 2;
                int kq = e & 3;
                int gm = m0 + m;
                if (gm < M)
                    v = *reinterpret_cast<const float4*>(Wt + (size_t)gm * K + k0 + kq * 4);
            }
            aReg[r] = v;
        }
    };
    auto stA = [&](int buf) {
        #pragma unroll
        for (int r = 0; r < AITER; ++r) {
            int e = tid + r * 256;
            if (AELE == 512 || e < AELE) {
                int m  = e >> 2;
                int kq = e & 3;
                float* p = &As[buf][(kq * 4) * ASTR + m];
                p[0 * ASTR] = f2tf32(aReg[r].x);
                p[1 * ASTR] = f2tf32(aReg[r].y);
                p[2 * ASTR] = f2tf32(aReg[r].z);
                p[3 * ASTR] = f2tf32(aReg[r].w);
            }
        }
    };
    auto issueB = [&](int k0, int buf) {
        if (KS == 1) {
            // 2048 floats = 512 x 16B ; 2 per thread. N % 128 == 0 assumed.
            #pragma unroll
            for (int r = 0; r < 2; ++r) {
                int o  = tid + r * 256;
                int k  = o >> 5;
                int c4 = (o & 31) * 4;
                uint32_t s = (uint32_t)__cvta_generic_to_shared(&Bs[buf][k * BSTR + c4]);
                cpasync16(s, Xb + (size_t)(k0 + k) * N + n0 + c4);
            }
        } else {
            #pragma unroll
            for (int r = 0; r < 8; ++r) {
                int k  = (tid >> 7) + 2 * r;
                int gk = k0 + k;
                int ic = gk / 9;
                int t  = gk - ic * 9;
                int tdy = (t >= 6) ? 2 : ((t >= 3) ? 1 : 0);
                int tdx = t - 3 * tdy;
                int iy = oy + tdy - pad;
                int ix = ox + tdx - pad;
                bool ok = nvalid && iy >= 0 && iy < IH && ix >= 0 && ix < IW;
                uint32_t s = (uint32_t)__cvta_generic_to_shared(&Bs[buf][k * BSTR + bn]);
                cpasync4(s, Xb + ((size_t)ic * IH + iy) * IW + ix, ok);
            }
        }
    };
    auto compute = [&](int buf) {
        #pragma unroll
        for (int ks = 0; ks < 2; ++ks) {
            const int kr = ks * 8 + lt;
            uint32_t a[FM][4];
            #pragma unroll
            for (int f = 0; f < FM; ++f) {
                int mr = mbase + f * 16 + lg;
                a[f][0] = __float_as_uint(As[buf][kr * ASTR + mr]);
                a[f][1] = __float_as_uint(As[buf][kr * ASTR + mr + 8]);
                a[f][2] = __float_as_uint(As[buf][(kr + 4) * ASTR + mr]);
                a[f][3] = __float_as_uint(As[buf][(kr + 4) * ASTR + mr + 8]);
            }
            #pragma unroll
            for (int nf = 0; nf < 4; ++nf) {
                int nc = nbase + nf * 8 + lg;
                uint32_t b0 = __float_as_uint(Bs[buf][kr * BSTR + nc]);
                uint32_t b1 = __float_as_uint(Bs[buf][(kr + 4) * BSTR + nc]);
                #pragma unroll
                for (int f = 0; f < FM; ++f)
                    mma_16x8x8(acc[f][nf], a[f], b0, b1);
            }
        }
    };

    const int kTiles = K / BK;
    issueB(0, 0); CP_COMMIT();
    ldA(0); stA(0);
    CP_WAIT0(); __syncthreads();

    for (int t = 0; t < kTiles; ++t) {
        if (t + 1 < kTiles) {
            issueB((t + 1) * BK, (t + 1) & 1); CP_COMMIT();
            ldA((t + 1) * BK);
        }
        compute(t & 1);
        if (t + 1 < kTiles) {
            stA((t + 1) & 1);
            CP_WAIT0(); __syncthreads();
        }
    }

    // ---- epilogue ----
    #pragma unroll
    for (int f = 0; f < FM; ++f) {
        int r0 = m0 + mbase + f * 16 + lg;
        #pragma unroll
        for (int nf = 0; nf < 4; ++nf) {
            int cb = n0 + nbase + nf * 8 + 2 * lt;
            #pragma unroll
            for (int rr = 0; rr < 2; ++rr) {
                int m = r0 + rr * 8;
                if (m >= M) continue;
                float bval = bias ? bias[m] : 0.f;
                #pragma unroll
                for (int cc = 0; cc < 2; ++cc) {
                    int n = cb + cc;
                    if (n >= N) continue;
                    Y[((size_t)bz * M + m) * N + n] = acc[f][nf][rr * 2 + cc] + bval;
                }
            }
        }
    }
}

// ---------------------------------------------------------------------------
// elementwise tf32 rounding (for conv inputs coming straight from harness)
// ---------------------------------------------------------------------------
__global__ void tf32round_kernel(const float* __restrict__ X,
                                 float* __restrict__ Y, int n)
{
    int i = blockIdx.x * 256 + threadIdx.x;
    if (i < n) Y[i] = f2tf32(X[i]);
}

// ---------------------------------------------------------------------------
// grouped 3x3 conv, smem-tiled
// ---------------------------------------------------------------------------
__global__ __launch_bounds__(256)
void dwconv2_kernel(const float* __restrict__ X,
                    const float* __restrict__ W,
                    float* __restrict__ Y)
{
    __shared__ float xs[2][34][35];
    __shared__ float ws[36];

    const int tile = blockIdx.x;
    const int g    = blockIdx.y;
    const int b    = blockIdx.z;
    const int ty0  = (tile / 3) * 32;
    const int tx0  = (tile % 3) * 32;
    const int tid  = threadIdx.x;

    if (tid < 36) ws[tid] = W[(size_t)g * 36 + tid];

    for (int e = tid; e < 2 * 34 * 34; e += 256) {
        int c  = e / (34 * 34);
        int r  = e - c * 34 * 34;
        int yy = r / 34, xx = r - yy * 34;
        int gy = ty0 + yy - 1, gx = tx0 + xx - 1;
        float v = 0.f;
        if (gy >= 0 && gy < Hh && gx >= 0 && gx < Ww)
            v = X[((size_t)b * C2 + 2 * g + c) * HW + gy * Ww + gx];
        xs[c][yy][xx] = v;
    }
    __syncthreads();

    const int x  = tid & 31;
    const int yb = (tid >> 5) * 4;
    #pragma unroll
    for (int j = 0; j < 4; ++j) {
        int y = yb + j;
        float a0 = 0.f, a1 = 0.f;
        #pragma unroll
        for (int c = 0; c < 2; ++c)
            #pragma unroll
            for (int ky = 0; ky < 3; ++ky)
                #pragma unroll
                for (int kx = 0; kx < 3; ++kx) {
                    float v = xs[c][y + ky][x + kx];
                    a0 += v * ws[c * 9 + ky * 3 + kx];
                    a1 += v * ws[18 + c * 9 + ky * 3 + kx];
                }
        size_t o = ((size_t)b * C2 + 2 * g) * HW + (ty0 + y) * Ww + tx0 + x;
        Y[o]      = a0;
        Y[o + HW] = a1;
    }
}

// cat = tf32([q ; y])  (conv-B input)
__global__ void cat_kernel(const float* __restrict__ QKV,
                           const float* __restrict__ Yin,
                           float* __restrict__ CAT)
{
    int idx = blockIdx.x * blockDim.x + threadIdx.x;
    if (idx >= Bn * C2 * HW) return;
    int p = idx % HW;
    int c = (idx / HW) % C2;
    int b = idx / (HW * C2);
    float v;
    if (c < Cc) v = QKV[((size_t)b * C2 + c) * HW + p];
    else        v = Yin[((size_t)b * Cc + (c - Cc)) * HW + p];
    CAT[idx] = f2tf32(v);
}

// 2x2 avg pool, 96 -> 48 (tf32 output, conv-B input)
__global__ void pool_kernel(const float* __restrict__ X, float* __restrict__ Y)
{
    int idx = blockIdx.x * blockDim.x + threadIdx.x;
    const int OHW = 48 * 48;
    if (idx >= Bn * C2 * OHW) return;
    int p  = idx % OHW;
    int bc = idx / OHW;
    int y = p / 48, x = p % 48;
    const float* xp = X + (size_t)bc * HW;
    float s = xp[(2 * y) * Ww + 2 * x] + xp[(2 * y) * Ww + 2 * x + 1]
            + xp[(2 * y + 1) * Ww + 2 * x] + xp[(2 * y + 1) * Ww + 2 * x + 1];
    Y[idx] = f2tf32(s * 0.25f);
}

// SC = tf32(SC * sigmoid(CAT + nearest_resize(K2)))   (conv-B input for k4)
__global__ void sigmul_kernel(float* __restrict__ SC,
                              const float* __restrict__ CAT,
                              const float* __restrict__ K2)
{
    int idx = blockIdx.x * blockDim.x + threadIdx.x;
    if (idx >= Bn * C2 * HW) return;
    int p  = idx % HW;
    int bc = idx / HW;
    int y = p / Ww, x = p % Ww;
    int iy = (y * 46) / 96;
    int ix = (x * 46) / 96;
    float s = CAT[idx] + K2[(size_t)bc * (46 * 46) + iy * 46 + ix];
    SC[idx] = f2tf32(SC[idx] / (1.f + expf(-s)));
}

// ---------------------------------------------------------------------------
// fused deformable conv; stores tf32(relu(out)) since FEAT only feeds pw conv
// ---------------------------------------------------------------------------
__global__ __launch_bounds__(128)
void deform_kernel(const float* __restrict__ Q,
                   const float* __restrict__ OFF,
                   const float* __restrict__ W,
                   const float* __restrict__ Bias,
                   float* __restrict__ Y)
{
    __shared__ float ws[24 * 216];
    const int g = blockIdx.y;
    const int b = blockIdx.z;
    const int tid = threadIdx.x;

    for (int e = tid; e < 24 * 216; e += 128) {
        int o = e / 216, r = e - o * 216;
        ws[e] = W[(size_t)(g * CG + o) * 216 + r];
    }
    __syncthreads();

    int p = blockIdx.x * 128 + tid;
    int y = p / Ww, x = p % Ww;
    const float* offb = OFF + (size_t)b * 18 * HW;

    float acc[24];
    #pragma unroll
    for (int o = 0; o < 24; ++o) acc[o] = Bias[g * CG + o];

    const float* qc = Q + ((size_t)b * C2 + g * CG) * HW;

    for (int t = 0; t < 9; ++t) {
        float dy = offb[(size_t)(2 * t) * HW + p];
        float dx = offb[(size_t)(2 * t + 1) * HW + p];
        float m  = 1.f / (1.f + expf(-offb[(size_t)t * HW + p]));
        float py = dy + (float)(y - 1 + t / 3);
        float px = dx + (float)(x - 1 + t % 3);
        float y0f = floorf(py), x0f = floorf(px);
        int   y0 = (int)y0f,    x0 = (int)x0f;
        float fy = py - y0f,    fx = px - x0f;
        float w00 = (1.f - fy) * (1.f - fx);
        float w01 = (1.f - fy) * fx;
        float w10 = fy * (1.f - fx);
        float w11 = fy * fx;
        bool vy0 = (y0 >= 0 && y0 <= Hh - 1), vy1 = (y0 + 1 >= 0 && y0 + 1 <= Hh - 1);
        bool vx0 = (x0 >= 0 && x0 <= Ww - 1), vx1 = (x0 + 1 >= 0 && x0 + 1 <= Ww - 1);
        int cy0 = min(max(y0, 0), Hh - 1),     cy1 = min(max(y0 + 1, 0), Hh - 1);
        int cx0 = min(max(x0, 0), Ww - 1),     cx1 = min(max(x0 + 1, 0), Ww - 1);
        int i00 = cy0 * Ww + cx0, i01 = cy0 * Ww + cx1;
        int i10 = cy1 * Ww + cx0, i11 = cy1 * Ww + cx1;
        w00 = (vy0 && vx0) ? w00 * m : 0.f;
        w01 = (vy0 && vx1) ? w01 * m : 0.f;
        w10 = (vy1 && vx0) ? w10 * m : 0.f;
        w11 = (vy1 && vx1) ? w11 * m : 0.f;

        #pragma unroll
        for (int i = 0; i < 24; ++i) {
            const float* qp = qc + (size_t)i * HW;
            float val = w00 * qp[i00] + w01 * qp[i01] + w10 * qp[i10] + w11 * qp[i11];
            const float* wr = &ws[i * 9 + t];
            #pragma unroll
            for (int o = 0; o < 24; ++o) acc[o] += val * wr[o * 216];
        }
    }
    #pragma unroll
    for (int o = 0; o < 24; ++o)
        Y[((size_t)b * Cc + g * CG + o) * HW + p] = f2tf32(fmaxf(acc[o], 0.f));
}

// ---------------------------------------------------------------------------
// row L2 norms
// ---------------------------------------------------------------------------
__global__ void rownorm_kernel(const float* __restrict__ QKV,
                               const float* __restrict__ Kb,
                               float* __restrict__ QN,
                               float* __restrict__ KN)
{
    int row   = blockIdx.x;
    int which = row / (Bn * Cc);
    row %= (Bn * Cc);
    int b = row / Cc, c = row % Cc;
    const float* src = which ? (Kb + ((size_t)b * Cc + c) * HW)
                             : (QKV + ((size_t)b * C2 + c) * HW);
    float s = 0.f;
    for (int n = threadIdx.x; n < HW; n += 256) {
        float v = src[n];
        s += v * v;
    }
    __shared__ float sm[256];
    sm[threadIdx.x] = s;
    __syncthreads();
    for (int d = 128; d > 0; d >>= 1) {
        if (threadIdx.x < d) sm[threadIdx.x] += sm[threadIdx.x + d];
        __syncthreads();
    }
    if (threadIdx.x == 0) {
        float nrm = fmaxf(sqrtf(sm[0]), 1e-12f);
        (which ? KN : QN)[b * Cc + c] = nrm;
    }
}

// ---------------------------------------------------------------------------
// attention: one block per (b,h).  K-head staged through smem.
// ---------------------------------------------------------------------------
#define CNK 384
__global__ __launch_bounds__(256)
void attn2_kernel(const float* __restrict__ QKV,
                  const float* __restrict__ Kb,
                  const float* __restrict__ QN,
                  const float* __restrict__ KN,
                  const float* __restrict__ TEMP,
                  float* __restrict__ ATTN)
{
    __shared__ float ks_[24][CNK + 8];
    __shared__ float logits[24][24];

    const int b = blockIdx.x >> 3;
    const int h = blockIdx.x & 7;
    const int tid  = threadIdx.x;
    const int wid  = tid >> 5;
    const int lane = tid & 31;

    const float* qh = QKV + ((size_t)b * C2 + h * HD) * HW;
    const float* kh = Kb  + ((size_t)b * Cc + h * HD) * HW;

    float acc[3][24];
    #pragma unroll
    for (int r = 0; r < 3; ++r)
        #pragma unroll
        for (int j = 0; j < 24; ++j) acc[r][j] = 0.f;

    const float* q0p = qh + (size_t)(3 * wid + 0) * HW;
    const float* q1p = qh + (size_t)(3 * wid + 1) * HW;
    const float* q2p = qh + (size_t)(3 * wid + 2) * HW;

    for (int n0 = 0; n0 < HW; n0 += CNK) {
        __syncthreads();
        for (int e = tid; e < 24 * (CNK / 4); e += 256) {
            int j = e / (CNK / 4);
            int c = e - j * (CNK / 4);
            float4 v = *reinterpret_cast<const float4*>(kh + (size_t)j * HW + n0 + c * 4);
            ks_[j][c * 4 + 0] = v.x;
            ks_[j][c * 4 + 1] = v.y;
            ks_[j][c * 4 + 2] = v.z;
            ks_[j][c * 4 + 3] = v.w;
        }
        __syncthreads();

        for (int i = lane; i < CNK; i += 32) {
            int n = n0 + i;
            float q0 = q0p[n], q1 = q1p[n], q2 = q2p[n];
            #pragma unroll
            for (int j = 0; j < 24; ++j) {
                float kv = ks_[j][i];
                acc[0][j] += q0 * kv;
                acc[1][j] += q1 * kv;
                acc[2][j] += q2 * kv;
            }
        }
    }

    #pragma unroll
    for (int r = 0; r < 3; ++r)
        #pragma unroll
        for (int j = 0; j < 24; ++j) {
            float v = acc[r][j];
            for (int o = 16; o > 0; o >>= 1) v += __shfl_down_sync(0xffffffffu, v, o);
            if (lane == 0) logits[wid * 3 + r][j] = v;
        }
    __syncthreads();

    if (tid < 24) {
        int i = tid;
        float qn = QN[b * Cc + h * HD + i];
        float tp = TEMP[h];
        float s[24];
        float mx = -1e30f;
        #pragma unroll
        for (int j = 0; j < 24; ++j) {
            s[j] = logits[i][j] / (qn * KN[b * Cc + h * HD + j]) * tp;
            mx = fmaxf(mx, s[j]);
        }
        float sum = 0.f;
        #pragma unroll
        for (int j = 0; j < 24; ++j) { s[j] = expf(s[j] - mx); sum += s[j]; }
        float inv = 1.f / sum;
        #pragma unroll
        for (int j = 0; j < 24; ++j)
            ATTN[(((size_t)b * NH + h) * HD + i) * HD + j] = s[j] * inv;
    }
}

// out = attn @ v ; stores tf32 (AO feeds proj conv)
__global__ void attnv_kernel(const float* __restrict__ ATTN,
                             const float* __restrict__ QKV,
                             float* __restrict__ AO)
{
    int h = blockIdx.y, b = blockIdx.z;
    int n = blockIdx.x * 256 + threadIdx.x;
    __shared__ float a_s[HD * HD];
    for (int e = threadIdx.x; e < HD * HD; e += 256)
        a_s[e] = ATTN[((size_t)b * NH + h) * HD * HD + e];
    __syncthreads();
    const float* vb = QKV + ((size_t)b * C2 + Cc + h * HD) * HW;
    float acc[HD] = {};
    #pragma unroll
    for (int j = 0; j < HD; ++j) {
        float vv = vb[(size_t)j * HW + n];
        #pragma unroll
        for (int i = 0; i < HD; ++i) acc[i] += a_s[i * HD + j] * vv;
    }
    #pragma unroll
    for (int i = 0; i < HD; ++i)
        AO[((size_t)b * Cc + h * HD + i) * HW + n] = f2tf32(acc[i]);
}

// ---------------------------------------------------------------------------
// launcher
// ---------------------------------------------------------------------------
extern "C" void kernel_launch(void* const* d_in, const int* in_sizes, int n_in,
                              void* d_out, int out_size)
{
    const float* x           = (const float*)d_in[0];
    const float* y           = (const float*)d_in[1];
    const float* temperature = (const float*)d_in[2];
    const float* qkv_w       = (const float*)d_in[3];
    const float* qkv_conv_w  = (const float*)d_in[4];
    const float* proj_w      = (const float*)d_in[5];
    const float* k2_w        = (const float*)d_in[6];
    const float* k3_w        = (const float*)d_in[7];
    const float* k4_w        = (const float*)d_in[8];
    const float* deform_w    = (const float*)d_in[9];
    const float* deform_b    = (const float*)d_in[10];
    const float* pw_w        = (const float*)d_in[11];
    const float* pw_b        = (const float*)d_in[12];
    float* out = (float*)d_out;

    float* S = nullptr;
    cudaGetSymbolAddress((void**)&S, g_scratch);
    float* QKV1 = S + OFF_QKV1;
    float* QKV  = S + OFF_QKV;
    float* CAT  = S + OFF_CAT;
    float* SC   = S + OFF_SC;
    float* POOL = S + OFF_POOL;
    float* K2   = S + OFF_K2;
    float* OFFb = S + OFF_OFF;
    float* FEAT = S + OFF_FEAT;
    float* Kb   = S + OFF_K;
    float* AO   = S + OFF_AO;
    float* QN   = S + OFF_QN;
    float* KN   = S + OFF_KN;
    float* ATTN = S + OFF_ATTN;
    float* XT   = S + OFF_XT;

    const int NE  = Bn * C2 * HW;
    const int NX  = Bn * Cc * HW;

    // 0) XT = tf32(x)
    tf32round_kernel<<<(NX + 255) / 256, 256>>>(x, XT, NX);
    // 1) qkv 1x1: 384 x 192 x 9216
    conv_mma<1, 4><<<dim3(HW / 128, C2 / 128, Bn), 256>>>(
        qkv_w, XT, QKV1, nullptr, C2, Cc, Hh, Ww, Hh, Ww, 0);
    // 2) grouped 3x3 (groups=192)
    dwconv2_kernel<<<dim3(9, 192, Bn), 256>>>(QKV1, qkv_conv_w, QKV);
    // 3) cat = tf32([q ; y])
    cat_kernel<<<(NE + 255) / 256, 256>>>(QKV, y, CAT);
    // 4) k3 conv 3x3 pad=1 (raw; sig multiply later)
    conv_mma<3, 4><<<dim3(HW / 128, C2 / 128, Bn), 256>>>(
        k3_w, CAT, SC, nullptr, C2, C2, Hh, Ww, Hh, Ww, 1);
    // 5) avg pool 2x2
    pool_kernel<<<(Bn * C2 * 48 * 48 + 255) / 256, 256>>>(CAT, POOL);
    // 6) k2 conv 3x3 pad=0 : 48x48 -> 46x46
    conv_mma<3, 4><<<dim3((46 * 46 + 127) / 128, C2 / 128, Bn), 256>>>(
        k2_w, POOL, K2, nullptr, C2, C2, 48, 48, 46, 46, 0);
    // 7) SC = tf32(SC * sigmoid(CAT + upsample(K2)))
    sigmul_kernel<<<(NE + 255) / 256, 256>>>(SC, CAT, K2);
    // 8) offset = conv3x3(sc, k4, pad=1), M=18
    conv_mma<3, 1><<<dim3(HW / 128, 1, Bn), 256>>>(
        k4_w, SC, OFFb, nullptr, 18, C2, Hh, Ww, Hh, Ww, 1);
    // 9) deformable conv -> FEAT = tf32(relu(deform))
    deform_kernel<<<dim3(HW / 128, Gg, Bn), 128>>>(QKV, OFFb, deform_w, deform_b, FEAT);
    // 10) k = 1x1(FEAT) + pw_b
    conv_mma<1, 4><<<dim3(HW / 128, (Cc + 127) / 128, Bn), 256>>>(
        pw_w, FEAT, Kb, pw_b, Cc, Cc, Hh, Ww, Hh, Ww, 0);
    // 11) row norms
    rownorm_kernel<<<2 * Bn * Cc, 256>>>(QKV, Kb, QN, KN);
    // 12) attention logits + softmax
    attn2_kernel<<<Bn * NH, 256>>>(QKV, Kb, QN, KN, temperature, ATTN);
    // 13) out = attn @ v
    attnv_kernel<<<dim3(HW / 256, NH, Bn), 256>>>(ATTN, QKV, AO);
    // 14) final 1x1 proj -> d_out
    conv_mma<1, 4><<<dim3(HW / 128, (Cc + 127) / 128, Bn), 256>>>(
        proj_w, AO, out, nullptr, Cc, Cc, Hh, Ww, Hh, Ww, 0);
}